// round 9
// baseline (speedup 1.0000x reference)
#include <cuda_runtime.h>
#include <cstddef>

// YOLOv3 head decode, fused, anchor-grouped mapping, 32-class chunking.
// Block = 384 threads = 128 consecutive positions x 3 anchors of one (b,level).
// Warps anchor-pure -> plane loads perfectly coalesced. Scores staged via
// dynamic smem in chunks of 32/32/16 classes; smem rows are 32 words
// (128B, float4-aligned) with XOR-swizzled 4-word groups for conflict-free
// STS.128/LDS.128. Box store folded into chunk-0 store phase: 6 barriers.
// Output: d_out = [boxes 16*22743*4][scores 16*22743*80].

#define NCLS 80
#define NTOT 22743
#define BATCH 16
#define EPSV 1e-7f
#define BLK 384
#define POSB 128              // positions per block
#define LBLK 61               // blocks per batch: 3 + 12 + 46
#define SSTRIDE 32            // smem words per row (128B, 16B-aligned)
#define SBOX (BLK * SSTRIDE)  // box buffer offset (words)
#define SMEM_WORDS (SBOX + BLK * 4)

// 4-word-group XOR swizzle: row r, group g (0..7) -> word offset
#define SSLOT(r, g) ((r) * SSTRIDE + (((g) ^ ((r) & 7)) << 2))

__constant__ float c_anch[3][3][2] = {
    {{116.0f, 90.0f}, {156.0f, 198.0f}, {373.0f, 326.0f}},
    {{ 30.0f, 61.0f}, { 62.0f,  45.0f}, { 59.0f, 119.0f}},
    {{ 10.0f, 13.0f}, { 16.0f,  30.0f}, { 33.0f,  23.0f}},
};

__device__ __forceinline__ float sigmoidf_fast(float x) {
    return __fdividef(1.0f, 1.0f + __expf(-x));
}

__global__ __launch_bounds__(BLK, 4)
void yolo_fused_kernel(const float* __restrict__ in0,
                       const float* __restrict__ in1,
                       const float* __restrict__ in2,
                       const float* __restrict__ im_size,
                       float* __restrict__ boxes,
                       float* __restrict__ scores)
{
    extern __shared__ float s[];   // [BLK*SSTRIDE] scores + [BLK*4] boxes

    const int tid = threadIdx.x;
    const int b   = blockIdx.x / LBLK;
    const int lid = blockIdx.x - b * LBLK;

    int level, pos0, HW, Wd, stride, off;
    const float* in;
    if (lid < 3)        { level = 0; pos0 = lid * POSB;        HW = 361;  Wd = 19; stride = 32; off = 0;    in = in0; }
    else if (lid < 15)  { level = 1; pos0 = (lid - 3) * POSB;  HW = 1444; Wd = 38; stride = 16; off = 1083; in = in1; }
    else                { level = 2; pos0 = (lid - 15) * POSB; HW = 5776; Wd = 76; stride = 8;  off = 5415; in = in2; }

    const int a   = tid / POSB;            // warp-pure anchor id
    const int i   = tid - a * POSB;
    const int pos = pos0 + i;
    const bool valid = (pos < HW);
    const int valid_rows = min(BLK, (HW - pos0) * 3);
    const int row_local  = i * 3 + a;
    const size_t row0 = (size_t)b * NTOT + off + (size_t)pos0 * 3;

    float conf = 0.0f;
    const float* p = in0;   // class-prob base for this thread's row

    if (valid) {
        const float* inb = in + (size_t)b * 258 * HW;

        float ip = sigmoidf_fast(inb[(size_t)a * HW + pos]);

        const float* f = inb + (size_t)(3 + a * 85) * HW + pos;
        float dx   = f[0];
        float dy   = f[(size_t)1 * HW];
        float dw   = f[(size_t)2 * HW];
        float dh   = f[(size_t)3 * HW];
        float tobj = f[(size_t)4 * HW];

        float obj = sigmoidf_fast(tobj);
        // new_obj = obj^0.6 * ip^0.4 (both strictly in (0,1))
        float new_obj = exp2f(0.6f * __log2f(obj) + 0.4f * __log2f(ip));
        // sigmoid(de_sigmoid(x)) == x for x in (EPS, 1-EPS); inputs are
        // N(0,1) so new_obj is far from both clip edges.
        conf = fminf(fmaxf(new_obj, EPSV), 1.0f);

        int hh = pos / Wd;
        int ww = pos - hh * Wd;
        float x = (1.05f * sigmoidf_fast(dx) + (float)ww - 0.025f) * (float)stride;
        float y = (1.05f * sigmoidf_fast(dy) + (float)hh - 0.025f) * (float)stride;
        float bw = __expf(dw) * c_anch[level][a][0];
        float bh = __expf(dh) * c_anch[level][a][1];

        float imh = im_size[b * 2 + 0];
        float imw = im_size[b * 2 + 1];
        const float inv = 1.0f / 608.0f;   // H*stride = 608 for all levels
        float sx = imw * inv;
        float sy = imh * inv;

        float x0 = fmaxf((x - 0.5f * bw) * sx, 0.0f);
        float y0 = fmaxf((y - 0.5f * bh) * sy, 0.0f);
        float x1 = fminf((x + 0.5f * bw) * sx, imw);
        float y1 = fminf((y + 0.5f * bh) * sy, imh);

        *reinterpret_cast<float4*>(&s[SBOX + row_local * 4]) =
            make_float4(x0, y0, x1, y1);

        p = f + (size_t)5 * HW;
    }

    // ---- chunk 0: classes [0,32) ----
    if (valid) {
        #pragma unroll
        for (int g = 0; g < 8; ++g) {
            int c = g * 4;
            float4 v;
            v.x = conf * sigmoidf_fast(p[(size_t)(c + 0) * HW]);
            v.y = conf * sigmoidf_fast(p[(size_t)(c + 1) * HW]);
            v.z = conf * sigmoidf_fast(p[(size_t)(c + 2) * HW]);
            v.w = conf * sigmoidf_fast(p[(size_t)(c + 3) * HW]);
            *reinterpret_cast<float4*>(&s[SSLOT(row_local, g)]) = v;
        }
    }
    __syncthreads();
    if (tid < valid_rows) {   // coalesced box store
        float4 v = *reinterpret_cast<const float4*>(&s[SBOX + tid * 4]);
        *reinterpret_cast<float4*>(&boxes[(row0 + tid) * 4]) = v;
    }
    #pragma unroll
    for (int k = 0; k < 8; ++k) {   // 384 rows x 32 floats, 8 lanes/row
        int idx = tid + k * BLK;
        int rr  = idx >> 3;
        int q   = idx & 7;
        if (rr < valid_rows) {
            float4 v = *reinterpret_cast<const float4*>(&s[SSLOT(rr, q)]);
            *reinterpret_cast<float4*>(&scores[(row0 + rr) * NCLS + q * 4]) = v;
        }
    }
    __syncthreads();

    // ---- chunk 1: classes [32,64) ----
    if (valid) {
        #pragma unroll
        for (int g = 0; g < 8; ++g) {
            int c = 32 + g * 4;
            float4 v;
            v.x = conf * sigmoidf_fast(p[(size_t)(c + 0) * HW]);
            v.y = conf * sigmoidf_fast(p[(size_t)(c + 1) * HW]);
            v.z = conf * sigmoidf_fast(p[(size_t)(c + 2) * HW]);
            v.w = conf * sigmoidf_fast(p[(size_t)(c + 3) * HW]);
            *reinterpret_cast<float4*>(&s[SSLOT(row_local, g)]) = v;
        }
    }
    __syncthreads();
    #pragma unroll
    for (int k = 0; k < 8; ++k) {
        int idx = tid + k * BLK;
        int rr  = idx >> 3;
        int q   = idx & 7;
        if (rr < valid_rows) {
            float4 v = *reinterpret_cast<const float4*>(&s[SSLOT(rr, q)]);
            *reinterpret_cast<float4*>(&scores[(row0 + rr) * NCLS + 32 + q * 4]) = v;
        }
    }
    __syncthreads();

    // ---- chunk 2: classes [64,80) ----
    if (valid) {
        #pragma unroll
        for (int g = 0; g < 4; ++g) {
            int c = 64 + g * 4;
            float4 v;
            v.x = conf * sigmoidf_fast(p[(size_t)(c + 0) * HW]);
            v.y = conf * sigmoidf_fast(p[(size_t)(c + 1) * HW]);
            v.z = conf * sigmoidf_fast(p[(size_t)(c + 2) * HW]);
            v.w = conf * sigmoidf_fast(p[(size_t)(c + 3) * HW]);
            *reinterpret_cast<float4*>(&s[SSLOT(row_local, g)]) = v;
        }
    }
    __syncthreads();
    #pragma unroll
    for (int k = 0; k < 4; ++k) {   // 384 rows x 16 floats, 4 lanes/row
        int idx = tid + k * BLK;
        int rr  = idx >> 2;
        int q   = idx & 3;
        if (rr < valid_rows) {
            float4 v = *reinterpret_cast<const float4*>(&s[SSLOT(rr, q)]);
            *reinterpret_cast<float4*>(&scores[(row0 + rr) * NCLS + 64 + q * 4]) = v;
        }
    }
}

extern "C" void kernel_launch(void* const* d_in, const int* in_sizes, int n_in,
                              void* d_out, int out_size)
{
    const float* out0 = (const float*)d_in[0];
    const float* out1 = (const float*)d_in[1];
    const float* out2 = (const float*)d_in[2];
    const float* imsz = (const float*)d_in[3];

    float* boxes  = (float*)d_out;
    float* scores = boxes + (size_t)BATCH * NTOT * 4;

    const int smem_bytes = SMEM_WORDS * 4;   // 55296 B
    cudaFuncSetAttribute(yolo_fused_kernel,
                         cudaFuncAttributeMaxDynamicSharedMemorySize,
                         smem_bytes);
    yolo_fused_kernel<<<BATCH * LBLK, BLK, smem_bytes>>>(
        out0, out1, out2, imsz, boxes, scores);
}

// round 10
// speedup vs baseline: 1.2404x; 1.2404x over previous
#include <cuda_runtime.h>
#include <cstddef>

// YOLOv3 head decode, fused, anchor-grouped mapping, small blocks.
// Block = 192 threads = 64 consecutive positions x 3 anchors of one (b,level).
// Warps anchor-pure -> plane loads perfectly coalesced. Scores staged via
// static smem in 16-class chunks (80B rows, 16B-aligned, near-conflict-free).
// Box store folded into chunk-0 store phase. 10 blocks/SM target.
// Output: d_out = [boxes 16*22743*4][scores 16*22743*80].

#define NCLS 80
#define NTOT 22743
#define BATCH 16
#define EPSV 1e-7f
#define BLK 192
#define POSB 64               // positions per block
#define LBLK 120              // blocks per batch: 6 + 23 + 91
#define SROW 20               // smem words per row per 16-class chunk (+4 pad)
#define SBOX (BLK * SROW)     // box buffer offset (words)

__constant__ float c_anch[3][3][2] = {
    {{116.0f, 90.0f}, {156.0f, 198.0f}, {373.0f, 326.0f}},
    {{ 30.0f, 61.0f}, { 62.0f,  45.0f}, { 59.0f, 119.0f}},
    {{ 10.0f, 13.0f}, { 16.0f,  30.0f}, { 33.0f,  23.0f}},
};

__device__ __forceinline__ float sigmoidf_fast(float x) {
    return __fdividef(1.0f, 1.0f + __expf(-x));
}

__global__ __launch_bounds__(BLK)
void yolo_fused_kernel(const float* __restrict__ in0,
                       const float* __restrict__ in1,
                       const float* __restrict__ in2,
                       const float* __restrict__ im_size,
                       float* __restrict__ boxes,
                       float* __restrict__ scores)
{
    __shared__ float s[SBOX + BLK * 4];   // 18.4 KB

    const int tid = threadIdx.x;
    const int b   = blockIdx.x / LBLK;
    const int lid = blockIdx.x - b * LBLK;

    int level, pos0, HW, Wd, stride, off;
    const float* in;
    if (lid < 6)        { level = 0; pos0 = lid * POSB;        HW = 361;  Wd = 19; stride = 32; off = 0;    in = in0; }
    else if (lid < 29)  { level = 1; pos0 = (lid - 6) * POSB;  HW = 1444; Wd = 38; stride = 16; off = 1083; in = in1; }
    else                { level = 2; pos0 = (lid - 29) * POSB; HW = 5776; Wd = 76; stride = 8;  off = 5415; in = in2; }

    const int a   = tid / POSB;            // warp-pure anchor id (2 warps each)
    const int i   = tid - a * POSB;
    const int pos = pos0 + i;
    const bool valid = (pos < HW);
    const int valid_rows = min(BLK, (HW - pos0) * 3);
    const int row_local  = i * 3 + a;
    const size_t row0 = (size_t)b * NTOT + off + (size_t)pos0 * 3;

    float conf = 0.0f;
    const float* p = in0;   // class-prob base for this thread's row

    if (valid) {
        const float* inb = in + (size_t)b * 258 * HW;

        float ip = sigmoidf_fast(inb[(size_t)a * HW + pos]);

        const float* f = inb + (size_t)(3 + a * 85) * HW + pos;
        float dx   = f[0];
        float dy   = f[(size_t)1 * HW];
        float dw   = f[(size_t)2 * HW];
        float dh   = f[(size_t)3 * HW];
        float tobj = f[(size_t)4 * HW];

        float obj = sigmoidf_fast(tobj);
        // new_obj = obj^0.6 * ip^0.4 (both strictly in (0,1))
        float new_obj = exp2f(0.6f * __log2f(obj) + 0.4f * __log2f(ip));
        // sigmoid(de_sigmoid(x)) == x for x in (EPS, 1-EPS); inputs are
        // N(0,1) so new_obj stays far from both clip edges.
        conf = fminf(fmaxf(new_obj, EPSV), 1.0f);

        int hh = pos / Wd;
        int ww = pos - hh * Wd;
        float x = (1.05f * sigmoidf_fast(dx) + (float)ww - 0.025f) * (float)stride;
        float y = (1.05f * sigmoidf_fast(dy) + (float)hh - 0.025f) * (float)stride;
        float bw = __expf(dw) * c_anch[level][a][0];
        float bh = __expf(dh) * c_anch[level][a][1];

        float imh = im_size[b * 2 + 0];
        float imw = im_size[b * 2 + 1];
        const float inv = 1.0f / 608.0f;   // H*stride = 608 for all levels
        float sx = imw * inv;
        float sy = imh * inv;

        float x0 = fmaxf((x - 0.5f * bw) * sx, 0.0f);
        float y0 = fmaxf((y - 0.5f * bh) * sy, 0.0f);
        float x1 = fminf((x + 0.5f * bw) * sx, imw);
        float y1 = fminf((y + 0.5f * bh) * sy, imh);

        *reinterpret_cast<float4*>(&s[SBOX + row_local * 4]) =
            make_float4(x0, y0, x1, y1);

        p = f + (size_t)5 * HW;
    }

    // scores: 5 chunks of 16 classes, staged through smem
    #pragma unroll
    for (int c0 = 0; c0 < NCLS; c0 += 16) {
        if (valid) {
            #pragma unroll
            for (int g = 0; g < 4; ++g) {
                int c = c0 + g * 4;
                float4 v;
                v.x = conf * sigmoidf_fast(p[(size_t)(c + 0) * HW]);
                v.y = conf * sigmoidf_fast(p[(size_t)(c + 1) * HW]);
                v.z = conf * sigmoidf_fast(p[(size_t)(c + 2) * HW]);
                v.w = conf * sigmoidf_fast(p[(size_t)(c + 3) * HW]);
                *reinterpret_cast<float4*>(&s[row_local * SROW + g * 4]) = v;
            }
        }
        __syncthreads();

        if (c0 == 0 && tid < valid_rows) {   // coalesced box store, once
            float4 v = *reinterpret_cast<const float4*>(&s[SBOX + tid * 4]);
            *reinterpret_cast<float4*>(&boxes[(row0 + tid) * 4]) = v;
        }

        // write BLK rows x 16 floats: 4 lanes/row, 64B runs
        #pragma unroll
        for (int k = 0; k < 4; ++k) {
            int idx = tid + k * BLK;
            int rr  = idx >> 2;
            int q   = idx & 3;
            if (rr < valid_rows) {
                float4 v = *reinterpret_cast<const float4*>(&s[rr * SROW + q * 4]);
                *reinterpret_cast<float4*>(&scores[(row0 + rr) * NCLS + c0 + q * 4]) = v;
            }
        }
        __syncthreads();
    }
}

extern "C" void kernel_launch(void* const* d_in, const int* in_sizes, int n_in,
                              void* d_out, int out_size)
{
    const float* out0 = (const float*)d_in[0];
    const float* out1 = (const float*)d_in[1];
    const float* out2 = (const float*)d_in[2];
    const float* imsz = (const float*)d_in[3];

    float* boxes  = (float*)d_out;
    float* scores = boxes + (size_t)BATCH * NTOT * 4;

    yolo_fused_kernel<<<BATCH * LBLK, BLK>>>(out0, out1, out2, imsz, boxes, scores);
}